// round 13
// baseline (speedup 1.0000x reference)
#include <cuda_runtime.h>
#include <cuda_bf16.h>
#include <cstdint>

#define N_ROWS 16384
#define DDIM   2048
#define KCODES 1024
#define MARGIN 4.0f

__device__ float g_enorm[KCODES];
__device__ float g_cmax[(size_t)N_ROWS * 8];
__device__ ulonglong2 g_cmask[(size_t)N_ROWS * 8];
__device__ int   g_best[N_ROWS];
__device__ int   g_qcount;
__device__ int   g_queue[N_ROWS];
__device__ __nv_bfloat16 g_eb[(size_t)KCODES * DDIM];

// ---------------------------------------------------------------------------
#define ROWB   80                  // 64B payload + 16B pad (ldmatrix conflict-free)
#define STG    (256 * ROWB)        // stage: A 128 rows + B 128 rows = 20480 B
#define SMEM_P1 (4 * STG)          // 81920 -> 2 CTA/SM

static __device__ __forceinline__ uint32_t smem_u32(const void* p) {
    uint32_t a;
    asm("{ .reg .u64 t; cvta.to.shared.u64 t, %1; cvt.u32.u64 %0, t; }"
        : "=r"(a) : "l"(p));
    return a;
}

#define LDSM_X4(r, addr)                                                     \
    asm volatile("ldmatrix.sync.aligned.m8n8.x4.shared.b16 {%0,%1,%2,%3}, [%4];" \
        : "=r"((r)[0]), "=r"((r)[1]), "=r"((r)[2]), "=r"((r)[3]) : "r"(addr))

#define MMA_BF16(d, a, b0, b1)                                               \
    asm volatile("mma.sync.aligned.m16n8k16.row.col.f32.bf16.bf16.f32 "      \
        "{%0,%1,%2,%3}, {%4,%5,%6,%7}, {%8,%9}, {%0,%1,%2,%3};"              \
        : "+f"((d)[0]), "+f"((d)[1]), "+f"((d)[2]), "+f"((d)[3])             \
        : "r"((a)[0]), "r"((a)[1]), "r"((a)[2]), "r"((a)[3]),                \
          "r"(b0), "r"(b1))

#define CP16(dst, src)                                                       \
    asm volatile("cp.async.ca.shared.global [%0], [%1], 16;"                 \
                 :: "r"(dst), "l"(src))
#define CP_COMMIT() asm volatile("cp.async.commit_group;" ::: "memory")
#define CP_WAIT2()  asm volatile("cp.async.wait_group 2;" ::: "memory")
#define CP_WAIT0()  asm volatile("cp.async.wait_group 0;" ::: "memory")

static __device__ __forceinline__ uint32_t packbf(float a, float b) {
    __nv_bfloat162 t = __floats2bfloat162_rn(a, b);
    uint32_t u; memcpy(&u, &t, 4); return u;
}

// ---------------------------------------------------------------------------
// codebook: fp32 -> bf16 + 0.5*||e||^2 in one pass; also resets the queue.
// ---------------------------------------------------------------------------
__global__ void conv_enorm_kernel(const float* __restrict__ e,
                                  __nv_bfloat16* __restrict__ eb) {
    int k = blockIdx.x;
    const float4* row = reinterpret_cast<const float4*>(e + (size_t)k * DDIM);
    uint2* drow = reinterpret_cast<uint2*>(eb + (size_t)k * DDIM);
    float s = 0.f;
#pragma unroll
    for (int r = 0; r < 2; r++) {
        int i = threadIdx.x + r * 256;
        float4 v = row[i];
        s += v.x * v.x + v.y * v.y + v.z * v.z + v.w * v.w;
        uint2 u = make_uint2(packbf(v.x, v.y), packbf(v.z, v.w));
        drow[i] = u;
    }
#pragma unroll
    for (int o = 16; o; o >>= 1) s += __shfl_xor_sync(0xffffffffu, s, o);
    __shared__ float ss[8];
    if ((threadIdx.x & 31) == 0) ss[threadIdx.x >> 5] = s;
    __syncthreads();
    if (threadIdx.x == 0) {
        float t = 0.f;
        for (int i = 0; i < 8; i++) t += ss[i];
        g_enorm[k] = 0.5f * t;
    }
    if (blockIdx.x == 0 && threadIdx.x == 0) g_qcount = 0;
}

// ---------------------------------------------------------------------------
// Pass 1: bf16 HMMA GEMM (128-thread CTA, 128x128 tile, 64x64 warp tile,
// KT=32, 4-stage pipeline). A fill: fp32 LDG + inline bf16 convert + STS
// (no separate x convert kernel). B fill: cp.async from g_eb.
// ---------------------------------------------------------------------------
__global__ __launch_bounds__(128, 2)
void pass1_gemm(const float* __restrict__ x) {
    extern __shared__ char smem[];
    const uint32_t sbase = smem_u32(smem);

    const int tid  = threadIdx.x;
    const int lane = tid & 31;
    const int wid  = tid >> 5;
    const int wm   = wid & 1;
    const int wn   = wid >> 1;
    const int brow  = blockIdx.y * 128;
    const int bcode = blockIdx.x * 128;
    const int cidx  = blockIdx.x;

    const __nv_bfloat16* eb = g_eb;

    float acc[4][8][4];
#pragma unroll
    for (int mi = 0; mi < 4; mi++)
#pragma unroll
        for (int ni = 0; ni < 8; ni++)
#pragma unroll
            for (int k = 0; k < 4; k++) acc[mi][ni][k] = 0.f;

    // A mapping: thread handles row = tid, 4 slots of 16B bf16 (= 32B fp32 each)
    // B mapping: thread handles 4 cp.async slots.
    auto issue = [&](int g) {
        if (g < 64) {
            const int d0 = g * 32;
            const uint32_t st = sbase + (g & 3) * STG;
            // ---- A: fp32 LDG (batched) -> bf16 -> STS ----
            const float* xr = x + (size_t)(brow + tid) * DDIM + d0;
            float4 v[8];
#pragma unroll
            for (int c = 0; c < 4; c++) {
                v[2 * c]     = *reinterpret_cast<const float4*>(xr + c * 8);
                v[2 * c + 1] = *reinterpret_cast<const float4*>(xr + c * 8 + 4);
            }
#pragma unroll
            for (int c = 0; c < 4; c++) {
                uint4 o;
                o.x = packbf(v[2*c].x,   v[2*c].y);
                o.y = packbf(v[2*c].z,   v[2*c].w);
                o.z = packbf(v[2*c+1].x, v[2*c+1].y);
                o.w = packbf(v[2*c+1].z, v[2*c+1].w);
                *reinterpret_cast<uint4*>(smem + (g & 3) * STG +
                                          tid * ROWB + c * 16) = o;
            }
            // ---- B: cp.async ----
#pragma unroll
            for (int r = 0; r < 4; r++) {
                int idx = tid + r * 128;          // 0..511
                int c   = idx & 3;
                int row = idx >> 2;               // 0..127
                CP16(st + (128 + row) * ROWB + c * 16,
                     eb + (size_t)(bcode + row) * DDIM + d0 + c * 8);
            }
        }
        CP_COMMIT();
    };

    issue(0); issue(1); issue(2);

    const uint32_t aRowOff = (uint32_t)(wm * 64 + (lane & 15)) * ROWB +
                             ((lane >> 4) << 4);
    const uint32_t bRowOff = (uint32_t)(128 + wn * 64 + ((lane >> 4) << 3) + (lane & 7)) * ROWB +
                             (((lane >> 3) & 1) << 4);

    for (int kt = 0; kt < 64; kt++) {
        CP_WAIT2();
        __syncthreads();
        issue(kt + 3);

        const uint32_t aB = sbase + (kt & 3) * STG;
#pragma unroll
        for (int kq = 0; kq < 2; kq++) {
            uint32_t aF[4][4];
#pragma unroll
            for (int mi = 0; mi < 4; mi++)
                LDSM_X4(aF[mi], aB + aRowOff + mi * 16 * ROWB + kq * 32);
#pragma unroll
            for (int nj = 0; nj < 4; nj++) {
                uint32_t bF[4];
                LDSM_X4(bF, aB + bRowOff + nj * 16 * ROWB + kq * 32);
#pragma unroll
                for (int mi = 0; mi < 4; mi++) {
                    MMA_BF16(acc[mi][nj * 2 + 0], aF[mi], bF[0], bF[1]);
                    MMA_BF16(acc[mi][nj * 2 + 1], aF[mi], bF[2], bF[3]);
                }
            }
        }
    }
    CP_WAIT0();
    __syncthreads();

    // ---- epilogue (overlays stage smem) ----
    float* ep_en = reinterpret_cast<float*>(smem);
    float* rmax  = reinterpret_cast<float*>(smem + 512);
    unsigned long long* rmask =
        reinterpret_cast<unsigned long long*>(smem + 1536);

    if (tid < 128) ep_en[tid] = g_enorm[bcode + tid];
    __syncthreads();

#pragma unroll
    for (int mi = 0; mi < 4; mi++)
#pragma unroll
        for (int half = 0; half < 2; half++) {
            int row = wm * 64 + mi * 16 + (lane >> 2) + half * 8;
            float m = -3.4e38f;
#pragma unroll
            for (int ni = 0; ni < 8; ni++)
#pragma unroll
                for (int e2 = 0; e2 < 2; e2++) {
                    int cl = wn * 64 + ni * 8 + (lane & 3) * 2 + e2;
                    m = fmaxf(m, acc[mi][ni][half * 2 + e2] - ep_en[cl]);
                }
            m = fmaxf(m, __shfl_xor_sync(0xffffffffu, m, 1));
            m = fmaxf(m, __shfl_xor_sync(0xffffffffu, m, 2));
            if ((lane & 3) == 0) rmax[row * 2 + wn] = m;
        }
    __syncthreads();

#pragma unroll
    for (int mi = 0; mi < 4; mi++)
#pragma unroll
        for (int half = 0; half < 2; half++) {
            int row = wm * 64 + mi * 16 + (lane >> 2) + half * 8;
            float th = fmaxf(rmax[row * 2], rmax[row * 2 + 1]) - MARGIN;
            unsigned long long mb = 0ull;
#pragma unroll
            for (int ni = 0; ni < 8; ni++)
#pragma unroll
                for (int e2 = 0; e2 < 2; e2++) {
                    int p = ni * 8 + (lane & 3) * 2 + e2;
                    float s = acc[mi][ni][half * 2 + e2] - ep_en[wn * 64 + p];
                    if (s >= th) mb |= (1ull << p);
                }
            mb |= __shfl_xor_sync(0xffffffffu, mb, 1);
            mb |= __shfl_xor_sync(0xffffffffu, mb, 2);
            if ((lane & 3) == 0) rmask[row * 2 + wn] = mb;
        }
    __syncthreads();

    if (tid < 128) {
        int grow = brow + tid;
        g_cmax[(size_t)grow * 8 + cidx] = fmaxf(rmax[tid * 2], rmax[tid * 2 + 1]);
        g_cmask[(size_t)grow * 8 + cidx] =
            make_ulonglong2(rmask[tid * 2], rmask[tid * 2 + 1]);
    }
}

// ---------------------------------------------------------------------------
// decide_fast: one thread per row, vectorized metadata loads.
// ---------------------------------------------------------------------------
__global__ __launch_bounds__(256)
void decide_fast(void) {
    const int row = blockIdx.x * 256 + threadIdx.x;

    const float4* cm4 = reinterpret_cast<const float4*>(&g_cmax[(size_t)row * 8]);
    float4 c0 = cm4[0], c1 = cm4[1];
    float cm[8] = {c0.x, c0.y, c0.z, c0.w, c1.x, c1.y, c1.z, c1.w};

    float gmax = -3.4e38f;
#pragma unroll
    for (int j = 0; j < 8; j++) gmax = fmaxf(gmax, cm[j]);
    const float thr = gmax - MARGIN;

    const ulonglong2* mkp = &g_cmask[(size_t)row * 8];
    int ncand = 0;
    int firstI = 0;
#pragma unroll 1
    for (int c8 = 0; c8 < 8; c8++) {
        if (cm[c8] < thr) continue;
        ulonglong2 mk = mkp[c8];
        int p0 = __popcll(mk.x), p1 = __popcll(mk.y);
        if (ncand == 0) {
            if (p0) firstI = c8 * 128 + __ffsll((long long)mk.x) - 1;
            else if (p1) firstI = c8 * 128 + 64 + __ffsll((long long)mk.y) - 1;
        }
        ncand += p0 + p1;
    }

    if (ncand == 1) {
        g_best[row] = firstI;
    } else {
        g_queue[atomicAdd(&g_qcount, 1)] = row;
    }
}

// ---------------------------------------------------------------------------
// rescue: persistent warps over the queue; exact fp32 rescore (4-way ILP).
// ---------------------------------------------------------------------------
__global__ __launch_bounds__(256, 4)
void rescue_kernel(const float* __restrict__ x, const float* __restrict__ e) {
    const int lane  = threadIdx.x & 31;
    const int wgid  = (blockIdx.x * 256 + threadIdx.x) >> 5;
    const int nwarp = (gridDim.x * 256) >> 5;
    const int qn    = g_qcount;

    for (int q = wgid; q < qn; q += nwarp) {
        const int row = g_queue[q];
        const float* cmp = &g_cmax[(size_t)row * 8];
        const ulonglong2* mkp = &g_cmask[(size_t)row * 8];

        float gmax = -3.4e38f;
#pragma unroll
        for (int j = 0; j < 8; j++) gmax = fmaxf(gmax, cmp[j]);
        const float thr = gmax - MARGIN;

        const float* xrow = x + (size_t)row * DDIM;
        float bestS = -3.4e38f;
        int   bestI = 0x7fffffff;
#pragma unroll 1
        for (int c8 = 0; c8 < 8; c8++) {
            if (cmp[c8] < thr) continue;
            ulonglong2 mk = mkp[c8];
#pragma unroll 1
            for (int half = 0; half < 2; half++) {
                unsigned long long m = half ? mk.y : mk.x;
                while (m) {
                    int b = __ffsll((long long)m) - 1;
                    m &= m - 1;
                    int c = c8 * 128 + half * 64 + b;
                    const float* er = e + (size_t)c * DDIM;
                    float p0 = 0.f, p1 = 0.f, p2 = 0.f, p3 = 0.f;
#pragma unroll
                    for (int j = 0; j < 16; j++) {
                        p0 = fmaf(xrow[(4*j+0)*32+lane], er[(4*j+0)*32+lane], p0);
                        p1 = fmaf(xrow[(4*j+1)*32+lane], er[(4*j+1)*32+lane], p1);
                        p2 = fmaf(xrow[(4*j+2)*32+lane], er[(4*j+2)*32+lane], p2);
                        p3 = fmaf(xrow[(4*j+3)*32+lane], er[(4*j+3)*32+lane], p3);
                    }
                    float p = (p0 + p1) + (p2 + p3);
#pragma unroll
                    for (int o = 16; o; o >>= 1)
                        p += __shfl_xor_sync(0xffffffffu, p, o);
                    float s = p - g_enorm[c];
                    if (s > bestS) { bestS = s; bestI = c; }
                }
            }
        }
        if (lane == 0) g_best[row] = bestI;
    }
}

// ---------------------------------------------------------------------------
__global__ __launch_bounds__(256)
void gather_kernel(const float* __restrict__ e, float* __restrict__ out,
                   int extra) {
    const int lane = threadIdx.x & 31;
    const int row  = blockIdx.x * 8 + (threadIdx.x >> 5);
    const int best = g_best[row];
    const float4* src = reinterpret_cast<const float4*>(e + (size_t)best * DDIM);
    float4* dst = reinterpret_cast<float4*>(out + (size_t)row * DDIM);
#pragma unroll
    for (int r = 0; r < 16; r++) dst[lane + r * 32] = src[lane + r * 32];
    if (lane == 0 && row < extra)
        out[(size_t)N_ROWS * DDIM + row] = (float)best;
}

__global__ void tail_spill(float* __restrict__ out, int extra) {
    float v = out[(size_t)N_ROWS * DDIM + (N_ROWS - 1)];
    for (int i = N_ROWS + blockIdx.x * blockDim.x + threadIdx.x; i < extra;
         i += gridDim.x * blockDim.x)
        out[(size_t)N_ROWS * DDIM + i] = v;
}

// ---------------------------------------------------------------------------
extern "C" void kernel_launch(void* const* d_in, const int* in_sizes, int n_in,
                              void* d_out, int out_size) {
    const float* x = (const float*)d_in[0];
    const float* e = (const float*)d_in[1];
    float* out = (float*)d_out;

    static __nv_bfloat16* eb_p = nullptr;
    if (!eb_p) {
        cudaGetSymbolAddress((void**)&eb_p, g_eb);
        cudaFuncSetAttribute(pass1_gemm,
                             cudaFuncAttributeMaxDynamicSharedMemorySize, SMEM_P1);
    }

    int extra = out_size - N_ROWS * DDIM;

    conv_enorm_kernel<<<KCODES, 512 / 2>>>(e, eb_p);

    dim3 g1(KCODES / 128, N_ROWS / 128);   // (8, 128) = 1024 CTAs
    pass1_gemm<<<g1, 128, SMEM_P1>>>(x);

    decide_fast<<<N_ROWS / 256, 256>>>();
    rescue_kernel<<<592, 256>>>(x, e);
    gather_kernel<<<N_ROWS / 8, 256>>>(e, out, extra);

    if (extra > N_ROWS)
        tail_spill<<<64, 256>>>(out, extra);
}

// round 14
// speedup vs baseline: 1.7933x; 1.7933x over previous
#include <cuda_runtime.h>
#include <cuda_bf16.h>
#include <cstdint>

#define N_ROWS 16384
#define DDIM   2048
#define KCODES 1024
#define MARGIN 4.0f

__device__ float g_enorm[KCODES];
__device__ float g_cmax[(size_t)N_ROWS * 8];
__device__ ulonglong2 g_cmask[(size_t)N_ROWS * 8];
__device__ int   g_best[N_ROWS];
__device__ unsigned long long g_bestkey[N_ROWS];
__device__ int   g_qcount;
__device__ int   g_queue[N_ROWS];
__device__ __nv_bfloat16 g_xb[(size_t)N_ROWS * DDIM];
__device__ __nv_bfloat16 g_eb[(size_t)KCODES * DDIM];

// ---------------------------------------------------------------------------
#define ROWB   80                  // 64B payload + 16B pad (ldmatrix conflict-free)
#define STG    (256 * ROWB)        // stage: A 128 rows + B 128 rows = 20480 B
#define SMEM_P1 (4 * STG)          // 81920 -> 2 CTA/SM

static __device__ __forceinline__ uint32_t smem_u32(const void* p) {
    uint32_t a;
    asm("{ .reg .u64 t; cvta.to.shared.u64 t, %1; cvt.u32.u64 %0, t; }"
        : "=r"(a) : "l"(p));
    return a;
}

#define LDSM_X4(r, addr)                                                     \
    asm volatile("ldmatrix.sync.aligned.m8n8.x4.shared.b16 {%0,%1,%2,%3}, [%4];" \
        : "=r"((r)[0]), "=r"((r)[1]), "=r"((r)[2]), "=r"((r)[3]) : "r"(addr))

#define MMA_BF16(d, a, b0, b1)                                               \
    asm volatile("mma.sync.aligned.m16n8k16.row.col.f32.bf16.bf16.f32 "      \
        "{%0,%1,%2,%3}, {%4,%5,%6,%7}, {%8,%9}, {%0,%1,%2,%3};"              \
        : "+f"((d)[0]), "+f"((d)[1]), "+f"((d)[2]), "+f"((d)[3])             \
        : "r"((a)[0]), "r"((a)[1]), "r"((a)[2]), "r"((a)[3]),                \
          "r"(b0), "r"(b1))

#define CP16(dst, src)                                                       \
    asm volatile("cp.async.ca.shared.global [%0], [%1], 16;"                 \
                 :: "r"(dst), "l"(src))
#define CP_COMMIT() asm volatile("cp.async.commit_group;" ::: "memory")
#define CP_WAIT2()  asm volatile("cp.async.wait_group 2;" ::: "memory")
#define CP_WAIT0()  asm volatile("cp.async.wait_group 0;" ::: "memory")

static __device__ __forceinline__ uint32_t packbf(float a, float b) {
    __nv_bfloat162 t = __floats2bfloat162_rn(a, b);
    uint32_t u; memcpy(&u, &t, 4); return u;
}
static __device__ __forceinline__ uint32_t encf(float f) {
    uint32_t u = __float_as_uint(f);
    return (u & 0x80000000u) ? ~u : (u | 0x80000000u);
}

// ---------------------------------------------------------------------------
__global__ void convert_kernel(const float* __restrict__ src,
                               __nv_bfloat16* __restrict__ dst, int n4) {
    for (int i = blockIdx.x * blockDim.x + threadIdx.x; i < n4;
         i += gridDim.x * blockDim.x) {
        float4 v = reinterpret_cast<const float4*>(src)[i];
        uint2 u = make_uint2(packbf(v.x, v.y), packbf(v.z, v.w));
        reinterpret_cast<uint2*>(dst)[i] = u;
    }
}

__global__ void conv_enorm_kernel(const float* __restrict__ e,
                                  __nv_bfloat16* __restrict__ eb) {
    int k = blockIdx.x;
    const float4* row = reinterpret_cast<const float4*>(e + (size_t)k * DDIM);
    uint2* drow = reinterpret_cast<uint2*>(eb + (size_t)k * DDIM);
    float s = 0.f;
#pragma unroll
    for (int r = 0; r < 2; r++) {
        int i = threadIdx.x + r * 256;
        float4 v = row[i];
        s += v.x * v.x + v.y * v.y + v.z * v.z + v.w * v.w;
        drow[i] = make_uint2(packbf(v.x, v.y), packbf(v.z, v.w));
    }
#pragma unroll
    for (int o = 16; o; o >>= 1) s += __shfl_xor_sync(0xffffffffu, s, o);
    __shared__ float ss[8];
    if ((threadIdx.x & 31) == 0) ss[threadIdx.x >> 5] = s;
    __syncthreads();
    if (threadIdx.x == 0) {
        float t = 0.f;
        for (int i = 0; i < 8; i++) t += ss[i];
        g_enorm[k] = 0.5f * t;
    }
    if (blockIdx.x == 0 && threadIdx.x == 0) g_qcount = 0;
}

// ---------------------------------------------------------------------------
// Pass 1: bf16 HMMA GEMM (128-thread CTA, 128x128 tile, 64x64 warp tile,
// KT=32, 4-stage cp.async, 2 CTA/SM). R12 configuration (reverted).
// ---------------------------------------------------------------------------
__global__ __launch_bounds__(128, 2)
void pass1_gemm(void) {
    extern __shared__ char smem[];
    const uint32_t sbase = smem_u32(smem);

    const int tid  = threadIdx.x;
    const int lane = tid & 31;
    const int wid  = tid >> 5;
    const int wm   = wid & 1;
    const int wn   = wid >> 1;
    const int brow  = blockIdx.y * 128;
    const int bcode = blockIdx.x * 128;
    const int cidx  = blockIdx.x;

    const __nv_bfloat16* xb = g_xb;
    const __nv_bfloat16* eb = g_eb;

    float acc[4][8][4];
#pragma unroll
    for (int mi = 0; mi < 4; mi++)
#pragma unroll
        for (int ni = 0; ni < 8; ni++)
#pragma unroll
            for (int k = 0; k < 4; k++) acc[mi][ni][k] = 0.f;

    auto issue = [&](int g) {
        if (g < 64) {
            const int d0 = g * 32;
            const uint32_t st = sbase + (g & 3) * STG;
#pragma unroll
            for (int r = 0; r < 8; r++) {
                int idx = tid + r * 128;
                int c   = idx & 3;
                int row = idx >> 2;
                const __nv_bfloat16* src = (row < 128)
                    ? xb + (size_t)(brow + row) * DDIM + d0 + c * 8
                    : eb + (size_t)(bcode + row - 128) * DDIM + d0 + c * 8;
                CP16(st + row * ROWB + c * 16, src);
            }
        }
        CP_COMMIT();
    };

    issue(0); issue(1); issue(2);

    const uint32_t aRowOff = (uint32_t)(wm * 64 + (lane & 15)) * ROWB +
                             ((lane >> 4) << 4);
    const uint32_t bRowOff = (uint32_t)(128 + wn * 64 + ((lane >> 4) << 3) + (lane & 7)) * ROWB +
                             (((lane >> 3) & 1) << 4);

    for (int kt = 0; kt < 64; kt++) {
        CP_WAIT2();
        __syncthreads();
        issue(kt + 3);

        const uint32_t aB = sbase + (kt & 3) * STG;
#pragma unroll
        for (int kq = 0; kq < 2; kq++) {
            uint32_t aF[4][4];
#pragma unroll
            for (int mi = 0; mi < 4; mi++)
                LDSM_X4(aF[mi], aB + aRowOff + mi * 16 * ROWB + kq * 32);
#pragma unroll
            for (int nj = 0; nj < 4; nj++) {
                uint32_t bF[4];
                LDSM_X4(bF, aB + bRowOff + nj * 16 * ROWB + kq * 32);
#pragma unroll
                for (int mi = 0; mi < 4; mi++) {
                    MMA_BF16(acc[mi][nj * 2 + 0], aF[mi], bF[0], bF[1]);
                    MMA_BF16(acc[mi][nj * 2 + 1], aF[mi], bF[2], bF[3]);
                }
            }
        }
    }
    CP_WAIT0();
    __syncthreads();

    // ---- epilogue (overlays stage smem) ----
    float* ep_en = reinterpret_cast<float*>(smem);
    float* rmax  = reinterpret_cast<float*>(smem + 512);
    unsigned long long* rmask =
        reinterpret_cast<unsigned long long*>(smem + 1536);

    if (tid < 128) ep_en[tid] = g_enorm[bcode + tid];
    __syncthreads();

#pragma unroll
    for (int mi = 0; mi < 4; mi++)
#pragma unroll
        for (int half = 0; half < 2; half++) {
            int row = wm * 64 + mi * 16 + (lane >> 2) + half * 8;
            float m = -3.4e38f;
#pragma unroll
            for (int ni = 0; ni < 8; ni++)
#pragma unroll
                for (int e2 = 0; e2 < 2; e2++) {
                    int cl = wn * 64 + ni * 8 + (lane & 3) * 2 + e2;
                    m = fmaxf(m, acc[mi][ni][half * 2 + e2] - ep_en[cl]);
                }
            m = fmaxf(m, __shfl_xor_sync(0xffffffffu, m, 1));
            m = fmaxf(m, __shfl_xor_sync(0xffffffffu, m, 2));
            if ((lane & 3) == 0) rmax[row * 2 + wn] = m;
        }
    __syncthreads();

#pragma unroll
    for (int mi = 0; mi < 4; mi++)
#pragma unroll
        for (int half = 0; half < 2; half++) {
            int row = wm * 64 + mi * 16 + (lane >> 2) + half * 8;
            float th = fmaxf(rmax[row * 2], rmax[row * 2 + 1]) - MARGIN;
            unsigned long long mb = 0ull;
#pragma unroll
            for (int ni = 0; ni < 8; ni++)
#pragma unroll
                for (int e2 = 0; e2 < 2; e2++) {
                    int p = ni * 8 + (lane & 3) * 2 + e2;
                    float s = acc[mi][ni][half * 2 + e2] - ep_en[wn * 64 + p];
                    if (s >= th) mb |= (1ull << p);
                }
            mb |= __shfl_xor_sync(0xffffffffu, mb, 1);
            mb |= __shfl_xor_sync(0xffffffffu, mb, 2);
            if ((lane & 3) == 0) rmask[row * 2 + wn] = mb;
        }
    __syncthreads();

    if (tid < 128) {
        int grow = brow + tid;
        g_cmax[(size_t)grow * 8 + cidx] = fmaxf(rmax[tid * 2], rmax[tid * 2 + 1]);
        g_cmask[(size_t)grow * 8 + cidx] =
            make_ulonglong2(rmask[tid * 2], rmask[tid * 2 + 1]);
    }
}

// ---------------------------------------------------------------------------
// decide_fast: one thread per row. Single-candidate rows resolved; others
// marked (-1), key zeroed, row queued.
// ---------------------------------------------------------------------------
__global__ __launch_bounds__(256)
void decide_fast(void) {
    const int row = blockIdx.x * 256 + threadIdx.x;

    const float4* cm4 = reinterpret_cast<const float4*>(&g_cmax[(size_t)row * 8]);
    float4 c0 = cm4[0], c1 = cm4[1];
    float cm[8] = {c0.x, c0.y, c0.z, c0.w, c1.x, c1.y, c1.z, c1.w};

    float gmax = -3.4e38f;
#pragma unroll
    for (int j = 0; j < 8; j++) gmax = fmaxf(gmax, cm[j]);
    const float thr = gmax - MARGIN;

    const ulonglong2* mkp = &g_cmask[(size_t)row * 8];
    int ncand = 0;
    int firstI = 0;
#pragma unroll 1
    for (int c8 = 0; c8 < 8; c8++) {
        if (cm[c8] < thr) continue;
        ulonglong2 mk = mkp[c8];
        int p0 = __popcll(mk.x), p1 = __popcll(mk.y);
        if (ncand == 0) {
            if (p0) firstI = c8 * 128 + __ffsll((long long)mk.x) - 1;
            else if (p1) firstI = c8 * 128 + 64 + __ffsll((long long)mk.y) - 1;
        }
        ncand += p0 + p1;
    }

    if (ncand == 1) {
        g_best[row] = firstI;
    } else {
        g_best[row] = -1;
        g_bestkey[row] = 0ull;
        g_queue[atomicAdd(&g_qcount, 1)] = row;
    }
}

// ---------------------------------------------------------------------------
// rescue: 4 warps per queued row, ordinal-strided over its candidates.
// Exact fp32 dot; result published via atomicMax on packed key.
// ---------------------------------------------------------------------------
__global__ __launch_bounds__(256, 4)
void rescue_kernel(const float* __restrict__ x, const float* __restrict__ e) {
    const int lane  = threadIdx.x & 31;
    const int gw    = (blockIdx.x * 256 + threadIdx.x) >> 5;
    const int nwarp = (gridDim.x * 256) >> 5;
    const int qn    = g_qcount;
    const int ntask = qn * 4;

    for (int t = gw; t < ntask; t += nwarp) {
        const int q    = t >> 2;
        const int ord0 = t & 3;
        const int row  = g_queue[q];

        const float* cmp = &g_cmax[(size_t)row * 8];
        const ulonglong2* mkp = &g_cmask[(size_t)row * 8];

        float gmax = -3.4e38f;
#pragma unroll
        for (int j = 0; j < 8; j++) gmax = fmaxf(gmax, cmp[j]);
        const float thr = gmax - MARGIN;

        const float* xrow = x + (size_t)row * DDIM;
        int ord = 0;
#pragma unroll 1
        for (int c8 = 0; c8 < 8; c8++) {
            if (cmp[c8] < thr) continue;
            ulonglong2 mk = mkp[c8];
#pragma unroll 1
            for (int half = 0; half < 2; half++) {
                unsigned long long m = half ? mk.y : mk.x;
                while (m) {
                    int b = __ffsll((long long)m) - 1;
                    m &= m - 1;
                    if ((ord & 3) == ord0) {
                        int c = c8 * 128 + half * 64 + b;
                        const float* er = e + (size_t)c * DDIM;
                        float p0 = 0.f, p1 = 0.f, p2 = 0.f, p3 = 0.f;
#pragma unroll
                        for (int j = 0; j < 16; j++) {
                            p0 = fmaf(xrow[(4*j+0)*32+lane], er[(4*j+0)*32+lane], p0);
                            p1 = fmaf(xrow[(4*j+1)*32+lane], er[(4*j+1)*32+lane], p1);
                            p2 = fmaf(xrow[(4*j+2)*32+lane], er[(4*j+2)*32+lane], p2);
                            p3 = fmaf(xrow[(4*j+3)*32+lane], er[(4*j+3)*32+lane], p3);
                        }
                        float p = (p0 + p1) + (p2 + p3);
#pragma unroll
                        for (int o = 16; o; o >>= 1)
                            p += __shfl_xor_sync(0xffffffffu, p, o);
                        float s = p - g_enorm[c];
                        if (lane == 0) {
                            unsigned long long key =
                                ((unsigned long long)encf(s) << 32) |
                                (uint32_t)(0x7fffffff - c);
                            atomicMax(&g_bestkey[row], key);
                        }
                    }
                    ord++;
                }
            }
        }
    }
}

// ---------------------------------------------------------------------------
// gather: streaming copy + queued-row key decode + index tail.
// ---------------------------------------------------------------------------
__global__ __launch_bounds__(256)
void gather_kernel(const float* __restrict__ e, float* __restrict__ out,
                   int extra) {
    const int lane = threadIdx.x & 31;
    const int row  = blockIdx.x * 8 + (threadIdx.x >> 5);
    int best = g_best[row];
    if (best < 0) {
        unsigned long long key = g_bestkey[row];
        best = 0x7fffffff - (int)(uint32_t)(key & 0xffffffffu);
    }
    const float4* src = reinterpret_cast<const float4*>(e + (size_t)best * DDIM);
    float4* dst = reinterpret_cast<float4*>(out + (size_t)row * DDIM);
#pragma unroll
    for (int r = 0; r < 16; r++) dst[lane + r * 32] = src[lane + r * 32];
    if (lane == 0 && row < extra)
        out[(size_t)N_ROWS * DDIM + row] = (float)best;
}

__global__ void tail_spill(float* __restrict__ out, int extra) {
    float v = out[(size_t)N_ROWS * DDIM + (N_ROWS - 1)];
    for (int i = N_ROWS + blockIdx.x * blockDim.x + threadIdx.x; i < extra;
         i += gridDim.x * blockDim.x)
        out[(size_t)N_ROWS * DDIM + i] = v;
}

// ---------------------------------------------------------------------------
extern "C" void kernel_launch(void* const* d_in, const int* in_sizes, int n_in,
                              void* d_out, int out_size) {
    const float* x = (const float*)d_in[0];
    const float* e = (const float*)d_in[1];
    float* out = (float*)d_out;

    static __nv_bfloat16* xb_p = nullptr;
    static __nv_bfloat16* eb_p = nullptr;
    if (!xb_p) {
        cudaGetSymbolAddress((void**)&xb_p, g_xb);
        cudaGetSymbolAddress((void**)&eb_p, g_eb);
        cudaFuncSetAttribute(pass1_gemm,
                             cudaFuncAttributeMaxDynamicSharedMemorySize, SMEM_P1);
    }

    int extra = out_size - N_ROWS * DDIM;

    convert_kernel<<<2048, 256>>>(x, xb_p, N_ROWS * DDIM / 4);
    conv_enorm_kernel<<<KCODES, 256>>>(e, eb_p);

    dim3 g1(KCODES / 128, N_ROWS / 128);   // (8, 128) = 1024 CTAs
    pass1_gemm<<<g1, 128, SMEM_P1>>>();

    decide_fast<<<N_ROWS / 256, 256>>>();
    rescue_kernel<<<592, 256>>>(x, e);
    gather_kernel<<<N_ROWS / 8, 256>>>(e, out, extra);

    if (extra > N_ROWS)
        tail_spill<<<64, 256>>>(out, extra);
}